// round 8
// baseline (speedup 1.0000x reference)
#include <cuda_runtime.h>
#include <cuda_bf16.h>
#include <math.h>
#include <stdint.h>

// Problem dims
#define BB   32
#define NN   256
#define DIMD 384
#define HH   6
#define DHD  64
#define MLPD 1536
#define DEPTH 12
#define INNERD 384
#define BN_ROWS (BB*NN)          // 8192
#define K3Q (3*DIMD)             // 1152
#define K3M (3*MLPD)             // 4608
#define NBH (BB*HH)              // 192
#define K3D (3*DHD)              // 192 (split K for dots)
#define K3N (3*NN)               // 768 (split K for attn*V)

// ---------------------------------------------------------------------------
// Device scratch
// ---------------------------------------------------------------------------
__device__ __align__(128) float g_x   [BN_ROWS*DIMD];
__device__ __align__(128) float g_dots[(size_t)NBH*NN*NN];
__device__ __align__(128) __nv_bfloat16 g_yp[(size_t)BN_ROWS*K3Q];
__device__ __align__(128) __nv_bfloat16 g_op[(size_t)BN_ROWS*K3Q];
__device__ __align__(128) __nv_bfloat16 g_hp[(size_t)BN_ROWS*K3M];
__device__ __align__(128) __nv_bfloat16 g_qs  [(size_t)NBH*NN*K3D];
__device__ __align__(128) __nv_bfloat16 g_ks  [(size_t)NBH*NN*K3D];
__device__ __align__(128) __nv_bfloat16 g_vsT [(size_t)NBH*DHD*K3N];
__device__ __align__(128) __nv_bfloat16 g_attns[(size_t)NBH*NN*K3N];
__device__ __align__(128) __nv_bfloat16 g_wqkvp[(size_t)DEPTH*1152*K3Q];
__device__ __align__(128) __nv_bfloat16 g_wop  [(size_t)DEPTH*384 *K3Q];
__device__ __align__(128) __nv_bfloat16 g_w1p  [(size_t)DEPTH*1536*K3Q];
__device__ __align__(128) __nv_bfloat16 g_w2p  [(size_t)DEPTH*384 *K3M];

// ---------------------------------------------------------------------------
// Helpers
// ---------------------------------------------------------------------------
__device__ __forceinline__ uint32_t cvta_s(const void* p) {
    uint32_t a;
    asm("{ .reg .u64 t; cvta.to.shared.u64 t, %1; cvt.u32.u64 %0, t; }"
        : "=r"(a) : "l"(p));
    return a;
}
#define CP_ASYNC16(dst, src) \
    asm volatile("cp.async.cg.shared.global [%0], [%1], 16;" :: "r"(dst), "l"(src))
#define CP_COMMIT() asm volatile("cp.async.commit_group;")
#define CP_WAIT0()  asm volatile("cp.async.wait_group 0;" ::: "memory")

__device__ __forceinline__ void mma16816(float* d, const uint32_t* a, const uint32_t* b) {
    asm volatile(
        "mma.sync.aligned.m16n8k16.row.col.f32.bf16.bf16.f32 "
        "{%0,%1,%2,%3}, {%4,%5,%6,%7}, {%8,%9}, {%0,%1,%2,%3};\n"
        : "+f"(d[0]), "+f"(d[1]), "+f"(d[2]), "+f"(d[3])
        : "r"(a[0]), "r"(a[1]), "r"(a[2]), "r"(a[3]), "r"(b[0]), "r"(b[1]));
}

__device__ __forceinline__ void bf_split(float v, __nv_bfloat16& hi, __nv_bfloat16& lo) {
    hi = __float2bfloat16(v);
    lo = __float2bfloat16(v - __bfloat162float(hi));
}

// ---------------------------------------------------------------------------
// Weight transpose + split: W[K,N] fp32 -> rows n of [hi(K)|hi(K)|lo(K)]
// ---------------------------------------------------------------------------
__global__ __launch_bounds__(256) void wconv_kernel(
    const float* __restrict__ W, __nv_bfloat16* __restrict__ out,
    int K, int N, int rowStride, int rowOff)
{
    __shared__ float tile[32][33];
    int k0 = blockIdx.y * 32, n0 = blockIdx.x * 32;
    int tx = threadIdx.x & 31, ty = threadIdx.x >> 5;
    #pragma unroll
    for (int i = 0; i < 4; i++) {
        int r = ty + i * 8;
        tile[r][tx] = W[(size_t)(k0 + r) * N + n0 + tx];
    }
    __syncthreads();
    #pragma unroll
    for (int i = 0; i < 4; i++) {
        int r = ty + i * 8;
        float w = tile[tx][r];
        __nv_bfloat16 hi, lo; bf_split(w, hi, lo);
        __nv_bfloat16* o = out + (size_t)(rowOff + n0 + r) * rowStride + k0 + tx;
        o[0]     = hi;
        o[K]     = hi;
        o[2 * K] = lo;
    }
}

// ---------------------------------------------------------------------------
// LayerNorm with split-bf16 output: y'[m] = [hi(384)|lo(384)|hi(384)]
// ---------------------------------------------------------------------------
__global__ __launch_bounds__(128) void ln_split_kernel(
    const float* __restrict__ x, const float* __restrict__ g,
    const float* __restrict__ b, __nv_bfloat16* __restrict__ yp)
{
    int row = blockIdx.x;
    int t = threadIdx.x;
    const float* xr = x + (size_t)row * DIMD;
    float v0 = xr[t], v1 = xr[t + 128], v2 = xr[t + 256];

    __shared__ float scratch[4];
    float s = v0 + v1 + v2;
    #pragma unroll
    for (int o = 16; o; o >>= 1) s += __shfl_xor_sync(0xffffffffu, s, o);
    if ((t & 31) == 0) scratch[t >> 5] = s;
    __syncthreads();
    s = scratch[0] + scratch[1] + scratch[2] + scratch[3];
    float mean = s * (1.0f / DIMD);

    float d0 = v0 - mean, d1 = v1 - mean, d2 = v2 - mean;
    float q = d0 * d0 + d1 * d1 + d2 * d2;
    __syncthreads();
    #pragma unroll
    for (int o = 16; o; o >>= 1) q += __shfl_xor_sync(0xffffffffu, q, o);
    if ((t & 31) == 0) scratch[t >> 5] = q;
    __syncthreads();
    q = scratch[0] + scratch[1] + scratch[2] + scratch[3];
    float rstd = rsqrtf(q * (1.0f / DIMD) + 1e-5f);

    __nv_bfloat16* yr = yp + (size_t)row * K3Q;
    #pragma unroll
    for (int seg = 0; seg < 3; seg++) {
        int c = t + seg * 128;
        float d = (seg == 0 ? d0 : seg == 1 ? d1 : d2);
        float v = d * rstd * g[c] + b[c];
        __nv_bfloat16 hi, lo; bf_split(v, hi, lo);
        yr[c]            = hi;
        yr[DIMD + c]     = lo;
        yr[2 * DIMD + c] = hi;
    }
}

// ---------------------------------------------------------------------------
// HMMA split-bf16 GEMM: C[M,N] = A'[M,K3] x W'[N,K3]^T, fp32 accum.
// 128x128x32 tile, 8 warps, cp.async double buffer.
// EPI 1: gelu(c+bias) -> split bf16. EPI 2: (c+bias)*ls+res -> fp32.
// EPI 3: QKV scatter (q*scale,k split-bf16; vT split-bf16).
// ---------------------------------------------------------------------------
#define GPITCH 40

template<int EPI>
__global__ __launch_bounds__(256) void tc_gemm(
    const __nv_bfloat16* __restrict__ A, const __nv_bfloat16* __restrict__ W,
    int K3, int N, int nchunks,
    float* __restrict__ Cf, __nv_bfloat16* __restrict__ Cs, int KsegOut,
    const float* __restrict__ bias, const float* __restrict__ ls,
    const float* __restrict__ res,
    const float* __restrict__ qscale,
    __nv_bfloat16* __restrict__ qs, __nv_bfloat16* __restrict__ ks,
    __nv_bfloat16* __restrict__ vsT)
{
    __shared__ __nv_bfloat16 As[2][128 * GPITCH];
    __shared__ __nv_bfloat16 Bs[2][128 * GPITCH];

    int tid = threadIdx.x, lane = tid & 31, wid = tid >> 5;
    __builtin_assume(tid < 256);
    int wm = wid & 1, wn = wid >> 1;
    int m0 = blockIdx.y * 128, n0 = blockIdx.x * 128;

    float acc[4][4][4] = {};

    auto load_chunk = [&](int c, int buf) {
        int k0 = c * 32;
        #pragma unroll
        for (int rep = 0; rep < 2; rep++) {
            int u = tid + rep * 256;
            int row = u >> 2, q = u & 3;
            uint32_t da = cvta_s(&As[buf][row * GPITCH + q * 8]);
            uint32_t db = cvta_s(&Bs[buf][row * GPITCH + q * 8]);
            CP_ASYNC16(da, A + (size_t)(m0 + row) * K3 + k0 + q * 8);
            CP_ASYNC16(db, W + (size_t)(n0 + row) * K3 + k0 + q * 8);
        }
        CP_COMMIT();
    };

    load_chunk(0, 0);
    for (int c = 0; c < nchunks; c++) {
        CP_WAIT0();
        __syncthreads();
        if (c + 1 < nchunks) load_chunk(c + 1, (c + 1) & 1);

        const __nv_bfloat16* Ab = As[c & 1];
        const __nv_bfloat16* Bb = Bs[c & 1];
        #pragma unroll
        for (int kk = 0; kk < 32; kk += 16) {
            int kc = kk + (lane & 3) * 2;
            uint32_t af[4][4], bf[4][2];
            #pragma unroll
            for (int mi = 0; mi < 4; mi++) {
                int r = wm * 64 + mi * 16 + (lane >> 2);
                af[mi][0] = *(const uint32_t*)&Ab[r * GPITCH + kc];
                af[mi][1] = *(const uint32_t*)&Ab[(r + 8) * GPITCH + kc];
                af[mi][2] = *(const uint32_t*)&Ab[r * GPITCH + kc + 8];
                af[mi][3] = *(const uint32_t*)&Ab[(r + 8) * GPITCH + kc + 8];
            }
            #pragma unroll
            for (int ni = 0; ni < 4; ni++) {
                int n = wn * 32 + ni * 8 + (lane >> 2);
                bf[ni][0] = *(const uint32_t*)&Bb[n * GPITCH + kc];
                bf[ni][1] = *(const uint32_t*)&Bb[n * GPITCH + kc + 8];
            }
            #pragma unroll
            for (int mi = 0; mi < 4; mi++)
                #pragma unroll
                for (int ni = 0; ni < 4; ni++)
                    mma16816(acc[mi][ni], af[mi], bf[ni]);
        }
    }

    #pragma unroll
    for (int mi = 0; mi < 4; mi++) {
        #pragma unroll
        for (int ni = 0; ni < 4; ni++) {
            int col = n0 + wn * 32 + ni * 8 + (lane & 3) * 2;
            #pragma unroll
            for (int hh = 0; hh < 2; hh++) {
                int m = m0 + wm * 64 + mi * 16 + (lane >> 2) + hh * 8;
                float v0 = acc[mi][ni][hh * 2 + 0];
                float v1 = acc[mi][ni][hh * 2 + 1];
                if (EPI == 1) {
                    #pragma unroll
                    for (int e = 0; e < 2; e++) {
                        float v = (e ? v1 : v0) + bias[col + e];
                        v = 0.5f * v * (1.0f + erff(v * 0.70710678118654752f));
                        __nv_bfloat16 hi, lo; bf_split(v, hi, lo);
                        __nv_bfloat16* o = Cs + (size_t)m * 3 * KsegOut + col + e;
                        o[0]           = hi;
                        o[KsegOut]     = lo;
                        o[2 * KsegOut] = hi;
                    }
                } else if (EPI == 2) {
                    size_t i0 = (size_t)m * N + col;
                    Cf[i0]     = (v0 + bias[col])     * ls[col]     + res[i0];
                    Cf[i0 + 1] = (v1 + bias[col + 1]) * ls[col + 1] + res[i0 + 1];
                } else if (EPI == 3) {
                    int b = m >> 8, il = m & 255;
                    #pragma unroll
                    for (int e = 0; e < 2; e++) {
                        float v = (e ? v1 : v0);
                        int n = col + e;
                        if (n < 384) {                 // Q (scale folded)
                            int h = n >> 6, d = n & 63;
                            v *= qscale[h];
                            __nv_bfloat16 hi, lo; bf_split(v, hi, lo);
                            __nv_bfloat16* o = qs + ((size_t)(b * HH + h) * NN + il) * K3D;
                            o[d]       = hi;
                            o[64 + d]  = lo;
                            o[128 + d] = hi;
                        } else if (n < 768) {          // K
                            int nn = n - 384, h = nn >> 6, d = nn & 63;
                            __nv_bfloat16 hi, lo; bf_split(v, hi, lo);
                            __nv_bfloat16* o = ks + ((size_t)(b * HH + h) * NN + il) * K3D;
                            o[d]       = hi;
                            o[64 + d]  = hi;
                            o[128 + d] = lo;
                        } else {                       // V transposed: vsT[bh][d][j]
                            int nn = n - 768, h = nn >> 6, d = nn & 63;
                            __nv_bfloat16 hi, lo; bf_split(v, hi, lo);
                            __nv_bfloat16* o = vsT + ((size_t)(b * HH + h) * DHD + d) * K3N;
                            o[il]       = hi;
                            o[256 + il] = hi;
                            o[512 + il] = lo;
                        }
                    }
                }
            }
        }
    }
}

// ---------------------------------------------------------------------------
// Batched HMMA dots: per z=(b,h): S[256,256] = qs[z] x ks[z]^T  (K3D=192)
// grid (2,2,192); writes fp32 dots.
// ---------------------------------------------------------------------------
__global__ __launch_bounds__(256) void dots_mma(
    const __nv_bfloat16* __restrict__ QS, const __nv_bfloat16* __restrict__ KS,
    float* __restrict__ dots)
{
    __shared__ __nv_bfloat16 As[2][128 * GPITCH];
    __shared__ __nv_bfloat16 Bs[2][128 * GPITCH];

    int z = blockIdx.z;
    const __nv_bfloat16* A = QS + (size_t)z * NN * K3D;
    const __nv_bfloat16* W = KS + (size_t)z * NN * K3D;
    float* C = dots + (size_t)z * NN * NN;

    int tid = threadIdx.x, lane = tid & 31, wid = tid >> 5;
    __builtin_assume(tid < 256);
    int wm = wid & 1, wn = wid >> 1;
    int m0 = blockIdx.y * 128, n0 = blockIdx.x * 128;
    float acc[4][4][4] = {};

    auto load_chunk = [&](int c, int buf) {
        int k0 = c * 32;
        #pragma unroll
        for (int rep = 0; rep < 2; rep++) {
            int u = tid + rep * 256;
            int row = u >> 2, q = u & 3;
            uint32_t da = cvta_s(&As[buf][row * GPITCH + q * 8]);
            uint32_t db = cvta_s(&Bs[buf][row * GPITCH + q * 8]);
            CP_ASYNC16(da, A + (size_t)(m0 + row) * K3D + k0 + q * 8);
            CP_ASYNC16(db, W + (size_t)(n0 + row) * K3D + k0 + q * 8);
        }
        CP_COMMIT();
    };

    load_chunk(0, 0);
    for (int c = 0; c < 6; c++) {
        CP_WAIT0();
        __syncthreads();
        if (c + 1 < 6) load_chunk(c + 1, (c + 1) & 1);

        const __nv_bfloat16* Ab = As[c & 1];
        const __nv_bfloat16* Bb = Bs[c & 1];
        #pragma unroll
        for (int kk = 0; kk < 32; kk += 16) {
            int kc = kk + (lane & 3) * 2;
            uint32_t af[4][4], bf[4][2];
            #pragma unroll
            for (int mi = 0; mi < 4; mi++) {
                int r = wm * 64 + mi * 16 + (lane >> 2);
                af[mi][0] = *(const uint32_t*)&Ab[r * GPITCH + kc];
                af[mi][1] = *(const uint32_t*)&Ab[(r + 8) * GPITCH + kc];
                af[mi][2] = *(const uint32_t*)&Ab[r * GPITCH + kc + 8];
                af[mi][3] = *(const uint32_t*)&Ab[(r + 8) * GPITCH + kc + 8];
            }
            #pragma unroll
            for (int ni = 0; ni < 4; ni++) {
                int n = wn * 32 + ni * 8 + (lane >> 2);
                bf[ni][0] = *(const uint32_t*)&Bb[n * GPITCH + kc];
                bf[ni][1] = *(const uint32_t*)&Bb[n * GPITCH + kc + 8];
            }
            #pragma unroll
            for (int mi = 0; mi < 4; mi++)
                #pragma unroll
                for (int ni = 0; ni < 4; ni++)
                    mma16816(acc[mi][ni], af[mi], bf[ni]);
        }
    }

    #pragma unroll
    for (int mi = 0; mi < 4; mi++)
        #pragma unroll
        for (int ni = 0; ni < 4; ni++) {
            int col = n0 + wn * 32 + ni * 8 + (lane & 3) * 2;
            #pragma unroll
            for (int hh = 0; hh < 2; hh++) {
                int m = m0 + wm * 64 + mi * 16 + (lane >> 2) + hh * 8;
                C[(size_t)m * NN + col]     = acc[mi][ni][hh * 2 + 0];
                C[(size_t)m * NN + col + 1] = acc[mi][ni][hh * 2 + 1];
            }
        }
}

// ---------------------------------------------------------------------------
// Softmax: pre-mix -> diag mask -> softmax -> post-mix, split-bf16 out.
// One block per (b,i), 256 threads (j). Single fused 6-way reductions.
// ---------------------------------------------------------------------------
__global__ __launch_bounds__(256) void softmax_split_kernel(
    const float* __restrict__ dots, const float* __restrict__ mp,
    const float* __restrict__ mq, __nv_bfloat16* __restrict__ attns)
{
    int b = blockIdx.x >> 8;
    int i = blockIdx.x & 255;
    int j = threadIdx.x;
    int lane = j & 31, wrp = j >> 5;

    __shared__ float smp[36], smq[36];
    __shared__ float red[8][6];
    if (j < 36) { smp[j] = mp[j]; smq[j] = mq[j]; }

    float raw[HH];
    #pragma unroll
    for (int h = 0; h < HH; h++)
        raw[h] = dots[(((size_t)(b * HH + h)) * NN + i) * NN + j];
    __syncthreads();

    float pm[HH];
    #pragma unroll
    for (int g = 0; g < HH; g++) {
        float s = 0.0f;
        #pragma unroll
        for (int h = 0; h < HH; h++) s = fmaf(raw[h], smp[h * HH + g], s);
        pm[g] = s;
    }
    if (j == i) {
        #pragma unroll
        for (int g = 0; g < HH; g++) pm[g] = -INFINITY;
    }

    // 6-way max reduce
    float mx[HH];
    #pragma unroll
    for (int g = 0; g < HH; g++) mx[g] = pm[g];
    #pragma unroll
    for (int o = 16; o; o >>= 1)
        #pragma unroll
        for (int g = 0; g < HH; g++)
            mx[g] = fmaxf(mx[g], __shfl_xor_sync(0xffffffffu, mx[g], o));
    if (lane == 0)
        #pragma unroll
        for (int g = 0; g < HH; g++) red[wrp][g] = mx[g];
    __syncthreads();
    #pragma unroll
    for (int g = 0; g < HH; g++) {
        float m = red[0][g];
        #pragma unroll
        for (int w = 1; w < 8; w++) m = fmaxf(m, red[w][g]);
        mx[g] = m;
    }
    __syncthreads();

    // exp + 6-way sum reduce
    float ex[HH], sm[HH];
    #pragma unroll
    for (int g = 0; g < HH; g++) { ex[g] = expf(pm[g] - mx[g]); sm[g] = ex[g]; }
    #pragma unroll
    for (int o = 16; o; o >>= 1)
        #pragma unroll
        for (int g = 0; g < HH; g++)
            sm[g] += __shfl_xor_sync(0xffffffffu, sm[g], o);
    if (lane == 0)
        #pragma unroll
        for (int g = 0; g < HH; g++) red[wrp][g] = sm[g];
    __syncthreads();
    float a[HH];
    #pragma unroll
    for (int g = 0; g < HH; g++) {
        float s = red[0][g];
        #pragma unroll
        for (int w = 1; w < 8; w++) s += red[w][g];
        a[g] = ex[g] / s;
    }

    // post-mix + split write: attns[(b*6+g, i)][j|256+j|512+j] = hi|lo|hi
    #pragma unroll
    for (int g = 0; g < HH; g++) {
        float s = 0.0f;
        #pragma unroll
        for (int h = 0; h < HH; h++) s = fmaf(a[h], smq[h * HH + g], s);
        __nv_bfloat16 hi, lo; bf_split(s, hi, lo);
        __nv_bfloat16* o = attns + ((size_t)(b * HH + g) * NN + i) * K3N;
        o[j]       = hi;
        o[256 + j] = lo;
        o[512 + j] = hi;
    }
}

// ---------------------------------------------------------------------------
// Batched HMMA attn*V: per z=(b,h): O[256,64] = attns[z] x vsT[z]^T (K3N=768)
// Tile 128x64, 8 warps (4M x 2N, 32x32 each). Writes g_op split-bf16.
// grid (2, 192).
// ---------------------------------------------------------------------------
__global__ __launch_bounds__(256) void attnv_mma(
    const __nv_bfloat16* __restrict__ AT, const __nv_bfloat16* __restrict__ VT,
    __nv_bfloat16* __restrict__ op)
{
    __shared__ __nv_bfloat16 As[2][128 * GPITCH];
    __shared__ __nv_bfloat16 Bs[2][64 * GPITCH];

    int z = blockIdx.y;
    int b = z / HH, h = z % HH;
    const __nv_bfloat16* A = AT + (size_t)z * NN * K3N;
    const __nv_bfloat16* W = VT + (size_t)z * DHD * K3N;

    int tid = threadIdx.x, lane = tid & 31, wid = tid >> 5;
    __builtin_assume(tid < 256);
    int wm = wid & 3, wn = wid >> 2;          // 4 (M) x 2 (N)
    int m0 = blockIdx.x * 128;
    float acc[2][4][4] = {};

    auto load_chunk = [&](int c, int buf) {
        int k0 = c * 32;
        #pragma unroll
        for (int rep = 0; rep < 2; rep++) {   // A: 128x32
            int u = tid + rep * 256;
            int row = u >> 2, q = u & 3;
            uint32_t da = cvta_s(&As[buf][row * GPITCH + q * 8]);
            CP_ASYNC16(da, A + (size_t)(m0 + row) * K3N + k0 + q * 8);
        }
        {                                      // B: 64x32
            int row = tid >> 2, q = tid & 3;
            uint32_t db = cvta_s(&Bs[buf][row * GPITCH + q * 8]);
            CP_ASYNC16(db, W + (size_t)row * K3N + k0 + q * 8);
        }
        CP_COMMIT();
    };

    load_chunk(0, 0);
    for (int c = 0; c < 24; c++) {
        CP_WAIT0();
        __syncthreads();
        if (c + 1 < 24) load_chunk(c + 1, (c + 1) & 1);

        const __nv_bfloat16* Ab = As[c & 1];
        const __nv_bfloat16* Bb = Bs[c & 1];
        #pragma unroll
        for (int kk = 0; kk < 32; kk += 16) {
            int kc = kk + (lane & 3) * 2;
            uint32_t af[2][4], bf[4][2];
            #pragma unroll
            for (int mi = 0; mi < 2; mi++) {
                int r = wm * 32 + mi * 16 + (lane >> 2);
                af[mi][0] = *(const uint32_t*)&Ab[r * GPITCH + kc];
                af[mi][1] = *(const uint32_t*)&Ab[(r + 8) * GPITCH + kc];
                af[mi][2] = *(const uint32_t*)&Ab[r * GPITCH + kc + 8];
                af[mi][3] = *(const uint32_t*)&Ab[(r + 8) * GPITCH + kc + 8];
            }
            #pragma unroll
            for (int ni = 0; ni < 4; ni++) {
                int n = wn * 32 + ni * 8 + (lane >> 2);
                bf[ni][0] = *(const uint32_t*)&Bb[n * GPITCH + kc];
                bf[ni][1] = *(const uint32_t*)&Bb[n * GPITCH + kc + 8];
            }
            #pragma unroll
            for (int mi = 0; mi < 2; mi++)
                #pragma unroll
                for (int ni = 0; ni < 4; ni++)
                    mma16816(acc[mi][ni], af[mi], bf[ni]);
        }
    }

    // Epilogue: o(i, d) -> op[b*256+i][h*64+d] split [hi|lo|hi] over 1152
    #pragma unroll
    for (int mi = 0; mi < 2; mi++)
        #pragma unroll
        for (int ni = 0; ni < 4; ni++) {
            int d0 = wn * 32 + ni * 8 + (lane & 3) * 2;
            #pragma unroll
            for (int hh = 0; hh < 2; hh++) {
                int i = m0 + wm * 32 + mi * 16 + (lane >> 2) + hh * 8;
                size_t row = (size_t)b * NN + i;
                #pragma unroll
                for (int e = 0; e < 2; e++) {
                    float v = acc[mi][ni][hh * 2 + e];
                    __nv_bfloat16 hi, lo; bf_split(v, hi, lo);
                    __nv_bfloat16* o = op + row * K3Q + h * DHD + d0 + e;
                    o[0]          = hi;
                    o[INNERD]     = lo;
                    o[2 * INNERD] = hi;
                }
            }
        }
}

// ---------------------------------------------------------------------------
// Launch
// ---------------------------------------------------------------------------
extern "C" void kernel_launch(void* const* d_in, const int* in_sizes, int n_in,
                              void* d_out, int out_size)
{
    const float* x    = (const float*)d_in[0];
    const float* ln1g = (const float*)d_in[1];
    const float* ln1b = (const float*)d_in[2];
    const float* wq   = (const float*)d_in[3];
    const float* wkv  = (const float*)d_in[4];
    const float* scl  = (const float*)d_in[5];
    const float* mp   = (const float*)d_in[6];
    const float* mq   = (const float*)d_in[7];
    const float* wo   = (const float*)d_in[8];
    const float* bo   = (const float*)d_in[9];
    const float* ls1  = (const float*)d_in[10];
    const float* ln2g = (const float*)d_in[11];
    const float* ln2b = (const float*)d_in[12];
    const float* w1   = (const float*)d_in[13];
    const float* b1   = (const float*)d_in[14];
    const float* w2   = (const float*)d_in[15];
    const float* b2   = (const float*)d_in[16];
    const float* ls2  = (const float*)d_in[17];

    float *gx, *gdots;
    __nv_bfloat16 *gyp, *gop, *ghp, *gqs, *gks, *gvsT, *gattns;
    __nv_bfloat16 *gwqkvp, *gwop, *gw1p, *gw2p;
    cudaGetSymbolAddress((void**)&gx,     g_x);
    cudaGetSymbolAddress((void**)&gdots,  g_dots);
    cudaGetSymbolAddress((void**)&gyp,    g_yp);
    cudaGetSymbolAddress((void**)&gop,    g_op);
    cudaGetSymbolAddress((void**)&ghp,    g_hp);
    cudaGetSymbolAddress((void**)&gqs,    g_qs);
    cudaGetSymbolAddress((void**)&gks,    g_ks);
    cudaGetSymbolAddress((void**)&gvsT,   g_vsT);
    cudaGetSymbolAddress((void**)&gattns, g_attns);
    cudaGetSymbolAddress((void**)&gwqkvp, g_wqkvp);
    cudaGetSymbolAddress((void**)&gwop,   g_wop);
    cudaGetSymbolAddress((void**)&gw1p,   g_w1p);
    cudaGetSymbolAddress((void**)&gw2p,   g_w2p);

    cudaMemcpyAsync(gx, x, (size_t)BN_ROWS * DIMD * sizeof(float),
                    cudaMemcpyDeviceToDevice, 0);

    // Weight conversion (transpose + bf16 split)
    for (int L = 0; L < DEPTH; L++) {
        wconv_kernel<<<dim3(384/32, 384/32), 256>>>(
            wq  + (size_t)L*DIMD*INNERD,   gwqkvp + (size_t)L*1152*K3Q, 384, 384,  K3Q, 0);
        wconv_kernel<<<dim3(768/32, 384/32), 256>>>(
            wkv + (size_t)L*DIMD*2*INNERD, gwqkvp + (size_t)L*1152*K3Q, 384, 768,  K3Q, 384);
        wconv_kernel<<<dim3(384/32, 384/32), 256>>>(
            wo  + (size_t)L*INNERD*DIMD,   gwop   + (size_t)L*384*K3Q,  384, 384,  K3Q, 0);
        wconv_kernel<<<dim3(1536/32, 384/32), 256>>>(
            w1  + (size_t)L*DIMD*MLPD,     gw1p   + (size_t)L*1536*K3Q, 384, 1536, K3Q, 0);
        wconv_kernel<<<dim3(384/32, 1536/32), 256>>>(
            w2  + (size_t)L*MLPD*DIMD,     gw2p   + (size_t)L*384*K3M,  1536, 384, K3M, 0);
    }

    for (int L = 0; L < DEPTH; L++) {
        const __nv_bfloat16* L_wqkvp = gwqkvp + (size_t)L*1152*K3Q;
        const __nv_bfloat16* L_wop   = gwop   + (size_t)L*384*K3Q;
        const __nv_bfloat16* L_w1p   = gw1p   + (size_t)L*1536*K3Q;
        const __nv_bfloat16* L_w2p   = gw2p   + (size_t)L*384*K3M;

        // Attention
        ln_split_kernel<<<BN_ROWS, 128>>>(gx, ln1g + L*DIMD, ln1b + L*DIMD, gyp);
        tc_gemm<3><<<dim3(1152/128, BN_ROWS/128), 256>>>(
            gyp, L_wqkvp, K3Q, 1152, K3Q/32, nullptr, nullptr, 0,
            nullptr, nullptr, nullptr, scl + L*HH, gqs, gks, gvsT);
        dots_mma<<<dim3(2, 2, NBH), 256>>>(gqs, gks, gdots);
        softmax_split_kernel<<<BB*NN, 256>>>(gdots, mp + L*HH*HH, mq + L*HH*HH, gattns);
        attnv_mma<<<dim3(2, NBH), 256>>>(gattns, gvsT, gop);
        tc_gemm<2><<<dim3(384/128, BN_ROWS/128), 256>>>(
            gop, L_wop, K3Q, 384, K3Q/32, gx, nullptr, 0,
            bo + L*DIMD, ls1 + L*DIMD, gx, nullptr, nullptr, nullptr, nullptr);

        // FFN
        ln_split_kernel<<<BN_ROWS, 128>>>(gx, ln2g + L*DIMD, ln2b + L*DIMD, gyp);
        tc_gemm<1><<<dim3(1536/128, BN_ROWS/128), 256>>>(
            gyp, L_w1p, K3Q, 1536, K3Q/32, nullptr, ghp, MLPD,
            b1 + L*MLPD, nullptr, nullptr, nullptr, nullptr, nullptr, nullptr);
        tc_gemm<2><<<dim3(384/128, BN_ROWS/128), 256>>>(
            ghp, L_w2p, K3M, 384, K3M/32, gx, nullptr, 0,
            b2 + L*DIMD, ls2 + L*DIMD, gx, nullptr, nullptr, nullptr, nullptr);
    }

    cudaMemcpyAsync(d_out, gx, (size_t)BN_ROWS * DIMD * sizeof(float),
                    cudaMemcpyDeviceToDevice, 0);
}